// round 14
// baseline (speedup 1.0000x reference)
#include <cuda_runtime.h>
#include <cstdint>

// Problem constants (fixed shapes from reference)
#define NROWS   65536            // BATCH*SEQ = 64*1024
#define FEATD   512
#define NBINS   32

// Global-pool occurrence counting (reference's int32 semantics drop `env`:
// left_shift(env,32) on int32 == 0 in XLA, so combined == keys).
#define HASH_BITS 17
#define HASH_SZ   (1 << HASH_BITS)
#define DUP_CAP   1024

// ---------------- scratch (device globals; no allocation allowed) ----------
__device__ float g_psum[1024 * 512];
__device__ float g_psq [1024 * 512];
__device__ float g_Pp  [512 * 32];     // P' = P / sigma  (row-major [feat][bin])
__device__ float g_biasp[16 * 32];
__device__ unsigned int g_keys[NROWS];
__device__ unsigned long long g_hash[HASH_SZ];
__device__ unsigned int g_hcnt[HASH_SZ];
__device__ int g_slot[NROWS];
__device__ int g_dupn;
__device__ int g_dup[DUP_CAP];

// ---------------------------------------------------------------------------
// Kernel 1: per-feature partial sums / squares + hash/counter reset.
// ---------------------------------------------------------------------------
__global__ void __launch_bounds__(128) sums_kernel(const float* __restrict__ x) {
    int t = threadIdx.x;
    int g = blockIdx.x * 128 + t;
    g_hash[g] = 0ull;
    g_hcnt[g] = 0u;
    if (g == 0) g_dupn = 0;

    const float4* xg = (const float4*)x + (size_t)blockIdx.x * 64 * 128 + t;
    float sx = 0.f, sy = 0.f, sz = 0.f, sw = 0.f;
    float qx = 0.f, qy = 0.f, qz = 0.f, qw = 0.f;
#pragma unroll 8
    for (int r = 0; r < 64; r++) {
        float4 v = xg[(size_t)r * 128];
        sx += v.x; sy += v.y; sz += v.z; sw += v.w;
        qx = fmaf(v.x, v.x, qx); qy = fmaf(v.y, v.y, qy);
        qz = fmaf(v.z, v.z, qz); qw = fmaf(v.w, v.w, qw);
    }
    ((float4*)g_psum)[blockIdx.x * 128 + t] = make_float4(sx, sy, sz, sw);
    ((float4*)g_psq )[blockIdx.x * 128 + t] = make_float4(qx, qy, qz, qw);
}

// ---------------------------------------------------------------------------
// Kernel 2: stats + Pp + bias partials (midreduce folded in).
// grid 16 x 1024. Phase 1 (coalesced): thread (pg=warp, f=b*32+lane) folds
// 32 of the 1024 block-partials. Phase 2: warp w reduces the 32 partials of
// feature b*32+w in fp64 (shfl tree), finalizes mean / inv-sigma, builds Pp.
// ---------------------------------------------------------------------------
__global__ void __launch_bounds__(1024) pp_kernel(const float* __restrict__ P) {
    __shared__ float ssum[32][33];
    __shared__ float ssq [32][33];
    __shared__ float sred[32][33];
    int tid = threadIdx.x, warp = tid >> 5, lane = tid & 31;

    // phase 1: coalesced fold of 32 block-partials
    {
        int f = blockIdx.x * 32 + lane;
        float s = 0.f, q = 0.f;
#pragma unroll 8
        for (int i = 0; i < 32; i++) {
            int p = warp * 32 + i;
            s += g_psum[p * 512 + f];
            q += g_psq [p * 512 + f];
        }
        ssum[warp][lane] = s;
        ssq [warp][lane] = q;
    }
    __syncthreads();

    // phase 2: warp w owns feature f = b*32 + w
    int f = blockIdx.x * 32 + warp;
    double sv = (double)ssum[lane][warp];
    double qv = (double)ssq [lane][warp];
#pragma unroll
    for (int off = 16; off > 0; off >>= 1) {
        sv += __shfl_down_sync(0xffffffffu, sv, off);
        qv += __shfl_down_sync(0xffffffffu, qv, off);
    }
    float meanf = 0.f, isig = 0.f;
    if (lane == 0) {
        const double Nd      = 65536.0;
        const double INV_N   = 1.0 / 65536.0;
        const double INV_NM1 = 1.0 / 65535.0;
        const double INV_TOT = 1.0 / 65536.0001;
        const double RATIO   = 65536.0 * INV_TOT;
        const double C1      = 1e-4 * 65536.0 * INV_TOT;
        double bm   = sv * INV_N;
        double bv   = (qv - Nd * bm * bm) * INV_NM1;
        double mean = bm * RATIO;
        double var  = (1e-4 + bv * Nd + bm * bm * C1) * INV_TOT;
        double v    = var + 1e-8;
        double r = (double)rsqrtf((float)v);
        r = r * (1.5 - 0.5 * v * r * r);
        meanf = (float)mean;
        isig  = (float)r;
    }
    meanf = __shfl_sync(0xffffffffu, meanf, 0);
    isig  = __shfl_sync(0xffffffffu, isig,  0);

    float pp = P[f * 32 + lane] * isig;
    g_Pp[f * 32 + lane] = pp;
    sred[warp][lane] = meanf * pp;
    __syncthreads();
    if (warp == 0) {
        float b = 0.f;
#pragma unroll
        for (int w = 0; w < 32; w++) b += sred[w][lane];
        g_biasp[blockIdx.x * 32 + lane] = b;
    }
}

// ---------------------------------------------------------------------------
// hash insert (helper): same key always resolves to the same slot.
// ---------------------------------------------------------------------------
__device__ __forceinline__ void hash_insert(int row, unsigned key) {
    unsigned long long tag = (1ull << 32) | (unsigned long long)key;
    unsigned h = (key * 2654435761u) >> (32 - HASH_BITS);
    for (;;) {
        unsigned long long prev = atomicCAS(&g_hash[h], 0ull, tag);
        if (prev == 0ull || prev == tag) {
            atomicAdd(&g_hcnt[h], 1u);
            g_slot[row] = (int)h;
            break;
        }
        h = (h + 1) & (HASH_SZ - 1);
    }
}

// ---------------------------------------------------------------------------
// Kernel 3: projection + sign-bit keys + PIPELINED hash insert (R12 core).
// fma phase: half-warp k-split, 2 bins/lane; warp w owns k [32w,32w+32).
// Reduction: single phase, warps 0-7 fold one row each, ballot keys, and
// drop them into a depth-2 smem ring. Warp 15 (highest wid) picks up the
// PREVIOUS iteration's 8 keys at the top of each iteration (ordering
// provided by the two block barriers) and issues the 8 hash inserts with
// 8 parallel lanes — atomic latency overlaps its upcoming fma phase.
// ---------------------------------------------------------------------------
#define P3_RB   8
#define P3_NBATCH (NROWS / P3_RB)    // 8192
// smem floats: 2 tiles (2*4096) + psum 8192 + bias 32 + kbuf 16
#define P3_SMEM  ((8192 + 8192 + 32 + 16) * 4)

__global__ void __launch_bounds__(512, 2) proj_kernel(const float* __restrict__ x) {
    extern __shared__ float smem[];
    float* xs0   = smem;             // 4096 floats (8 rows x 512)
    float* xs1   = smem + 4096;
    float* psum  = smem + 8192;      // [row][sub 0..31][bin 0..31]
    float* sbias = smem + 16384;     // 32 floats
    unsigned* kbuf = (unsigned*)(smem + 16416);   // [2][8] key ring

    int tid  = threadIdx.x;
    int warp = tid >> 5;
    int lane = tid & 31;
    int half = lane >> 4;            // 0: k-sub lo, 1: k-sub hi
    int b0   = (lane & 15) << 1;     // first of this lane's two bins
    int sub  = (warp << 1) | half;   // global k-sub index 0..31 (16 k each)

    if (tid < NBINS) {
        float b = 0.f;
#pragma unroll
        for (int p = 0; p < 16; p++) b += g_biasp[p * 32 + tid];
        sbias[tid] = b;
    }

    // ppd0[i]/ppd1[i]: Pp k-pair (16*sub+2i, +1) for bins b0 / b0+1
    unsigned long long ppd0[8], ppd1[8];
    int k0 = sub << 4;
#pragma unroll
    for (int i = 0; i < 8; i++) {
        int k = k0 + 2 * i;
        float a0 = g_Pp[k * NBINS + b0],     a1 = g_Pp[(k + 1) * NBINS + b0];
        float c0 = g_Pp[k * NBINS + b0 + 1], c1 = g_Pp[(k + 1) * NBINS + b0 + 1];
        asm("mov.b64 %0, {%1, %2};" : "=l"(ppd0[i]) : "f"(a0), "f"(a1));
        asm("mov.b64 %0, {%1, %2};" : "=l"(ppd1[i]) : "f"(c0), "f"(c1));
    }

    unsigned sb0a = (unsigned)__cvta_generic_to_shared(xs0);
    unsigned sb1a = (unsigned)__cvta_generic_to_shared(xs1);

    // prologue: stream first tile (1024 float4, 512 threads -> 2 each)
    {
        const float4* xg = (const float4*)(x + (size_t)blockIdx.x * P3_RB * FEATD);
#pragma unroll
        for (int i = 0; i < 2; i++) {
            unsigned d = sb0a + (tid + 512 * i) * 16;
            asm volatile("cp.async.cg.shared.global [%0], [%1], 16;"
                         :: "r"(d), "l"(xg + tid + 512 * i));
        }
        asm volatile("cp.async.commit_group;");
        asm volatile("cp.async.wait_group 0;" ::: "memory");
    }
    __syncthreads();

    int cur = 0, it = 0;

    for (int batch = blockIdx.x; batch < P3_NBATCH; batch += gridDim.x, it++) {
        int nb = batch + gridDim.x;
        if (nb < P3_NBATCH) {
            const float4* xg = (const float4*)(x + (size_t)nb * P3_RB * FEATD);
            unsigned dst = cur ? sb0a : sb1a;
#pragma unroll
            for (int i = 0; i < 2; i++) {
                unsigned d = dst + (tid + 512 * i) * 16;
                asm volatile("cp.async.cg.shared.global [%0], [%1], 16;"
                             :: "r"(d), "l"(xg + tid + 512 * i));
            }
            asm volatile("cp.async.commit_group;");
        }

        // warp 15: pick up previous iteration's keys, issue inserts.
        // Barriers of iteration it-1 order kbuf writes before these reads;
        // slot (it-1)&1 is not rewritten until iteration it+1 (depth-2 safe).
        if (warp == 15 && it > 0 && lane < P3_RB) {
            unsigned k = kbuf[((it - 1) & 1) * P3_RB + lane];
            hash_insert((batch - gridDim.x) * P3_RB + lane, k);
        }

        const float* xsc = cur ? xs1 : xs0;
#pragma unroll
        for (int r = 0; r < P3_RB; r++) {
            const ulonglong2* xp = (const ulonglong2*)(xsc + r * FEATD + k0);
            unsigned long long a0 = 0ull, a1 = 0ull, c0 = 0ull, c1 = 0ull;
#pragma unroll
            for (int i = 0; i < 4; i++) {
                ulonglong2 v = xp[i];
                asm("fma.rn.f32x2 %0, %1, %2, %0;"
                    : "+l"(a0) : "l"(v.x), "l"(ppd0[2 * i]));
                asm("fma.rn.f32x2 %0, %1, %2, %0;"
                    : "+l"(a1) : "l"(v.y), "l"(ppd0[2 * i + 1]));
                asm("fma.rn.f32x2 %0, %1, %2, %0;"
                    : "+l"(c0) : "l"(v.x), "l"(ppd1[2 * i]));
                asm("fma.rn.f32x2 %0, %1, %2, %0;"
                    : "+l"(c1) : "l"(v.y), "l"(ppd1[2 * i + 1]));
            }
            unsigned long long at, ct;
            asm("add.rn.f32x2 %0, %1, %2;" : "=l"(at) : "l"(a0), "l"(a1));
            asm("add.rn.f32x2 %0, %1, %2;" : "=l"(ct) : "l"(c0), "l"(c1));
            float alo, ahi, clo, chi;
            asm("mov.b64 {%0, %1}, %2;" : "=f"(alo), "=f"(ahi) : "l"(at));
            asm("mov.b64 {%0, %1}, %2;" : "=f"(clo), "=f"(chi) : "l"(ct));
            float2 pr = make_float2(alo + ahi, clo + chi);
            *(float2*)(psum + ((r * 32 + sub) * 32 + b0)) = pr;
        }
        __syncthreads();   // psum complete

        // single reduction phase: warp w (w<8) folds row w, ballots the key
        if (warp < P3_RB) {
            const float* pr = psum + warp * 32 * 32 + lane;
            float s0 = 0.f, s1 = 0.f, s2 = 0.f, s3 = 0.f;
#pragma unroll
            for (int c = 0; c < 8; c++) {
                s0 += pr[(c)      * 32];
                s1 += pr[(c + 8)  * 32];
                s2 += pr[(c + 16) * 32];
                s3 += pr[(c + 24) * 32];
            }
            float s = (s0 + s1) + (s2 + s3);
            unsigned key = __ballot_sync(0xffffffffu, s > sbias[lane]);
            if (lane == 0) {
                g_keys[batch * P3_RB + warp] = key;
                kbuf[(it & 1) * P3_RB + warp] = key;
            }
        }

        if (nb < P3_NBATCH)
            asm volatile("cp.async.wait_group 0;" ::: "memory");
        __syncthreads();   // next tile visible + psum WAR-safe + kbuf ordered
        cur ^= 1;
    }

    // tail: last iteration's keys (it-1 after loop exit)
    if (warp == 15 && it > 0 && lane < P3_RB) {
        int lastBatch = blockIdx.x + (it - 1) * gridDim.x;
        unsigned k = kbuf[((it - 1) & 1) * P3_RB + lane];
        hash_insert(lastBatch * P3_RB + lane, k);
    }
}

// ---------------------------------------------------------------------------
// Kernel 4: emit rewards for unique keys (count==1 -> 1.0); collect dup rows.
// ---------------------------------------------------------------------------
__global__ void __launch_bounds__(256) emit_kernel(float* __restrict__ out) {
    int i = blockIdx.x * 256 + threadIdx.x;
    if (g_hcnt[g_slot[i]] == 1u) {
        out[i] = 1.0f;
    } else {
        int d = atomicAdd(&g_dupn, 1);
        if (d < DUP_CAP) g_dup[d] = i;
    }
}

// ---------------------------------------------------------------------------
// Kernel 5: exact occurrence rank for duplicated rows (rare; ~2 expected).
// ---------------------------------------------------------------------------
__global__ void __launch_bounds__(256) dupfix_kernel(float* __restrict__ out) {
    __shared__ int red[256];
    int n = g_dupn;
    if (n > DUP_CAP) n = DUP_CAP;
    int t = threadIdx.x;
    for (int d = blockIdx.x; d < n; d += gridDim.x) {
        int i = g_dup[d];
        unsigned key = g_keys[i];
        int c = 0;
        for (int j = t; j <= i; j += 256) c += (g_keys[j] == key) ? 1 : 0;
        red[t] = c;
        __syncthreads();
#pragma unroll
        for (int off = 128; off > 0; off >>= 1) {
            if (t < off) red[t] += red[t + off];
            __syncthreads();
        }
        if (t == 0) out[i] = rsqrtf((float)red[0]);
        __syncthreads();
    }
}

// ---------------------------------------------------------------------------
extern "C" void kernel_launch(void* const* d_in, const int* in_sizes, int n_in,
                              void* d_out, int out_size) {
    const float* x = (const float*)d_in[0];   // features  [64,1024,512]
    const float* P = (const float*)d_in[1];   // projection [512,32]
    if (n_in >= 2 && in_sizes[0] < in_sizes[1]) {
        const float* t = x; x = P; P = t;
    }
    float* out = (float*)d_out;

    cudaFuncSetAttribute(proj_kernel,
                         cudaFuncAttributeMaxDynamicSharedMemorySize, P3_SMEM);

    sums_kernel   <<<1024, 128>>>(x);
    pp_kernel     <<<16,   1024>>>(P);
    proj_kernel   <<<296,  512, P3_SMEM>>>(x);
    emit_kernel   <<<NROWS / 256, 256>>>(out);
    dupfix_kernel <<<16,   256>>>(out);
}

// round 15
// speedup vs baseline: 1.2795x; 1.2795x over previous
#include <cuda_runtime.h>
#include <cstdint>

// Problem constants (fixed shapes from reference)
#define NROWS   65536            // BATCH*SEQ = 64*1024
#define FEATD   512
#define NBINS   32

// Global-pool occurrence counting (reference's int32 semantics drop `env`:
// left_shift(env,32) on int32 == 0 in XLA, so combined == keys).
// Hash entry packs key and count: entry = ((u64)key << 18) | count.
// Empty slot == 0 (count==0). Claiming CAS writes count=1 directly, so the
// common case (unique key) costs ONE atomic.
#define HASH_BITS 18
#define HASH_SZ   (1 << HASH_BITS)
#define CNT_MASK  0x3FFFFull
#define DUP_CAP   1024

// ---------------- scratch (device globals; no allocation allowed) ----------
__device__ float g_psum[1024 * 512];
__device__ float g_psq [1024 * 512];
__device__ float g_psum2[16 * 512];
__device__ float g_psq2 [16 * 512];
__device__ float g_Pp  [512 * 32];     // P' = P / sigma  (row-major [feat][bin])
__device__ float g_biasp[16 * 32];
__device__ unsigned int g_keys[NROWS];
__device__ unsigned long long g_hash[HASH_SZ];
__device__ int g_slot[NROWS];
__device__ int g_dupn;
__device__ int g_dup[DUP_CAP];

// ---------------------------------------------------------------------------
// Kernel 1: per-feature partial sums / squares + hash/counter reset
// (131072 threads x 2 entries == HASH_SZ).
// ---------------------------------------------------------------------------
__global__ void __launch_bounds__(128) sums_kernel(const float* __restrict__ x) {
    int t = threadIdx.x;
    int g = blockIdx.x * 128 + t;
    g_hash[2 * g]     = 0ull;
    g_hash[2 * g + 1] = 0ull;
    if (g == 0) g_dupn = 0;

    const float4* xg = (const float4*)x + (size_t)blockIdx.x * 64 * 128 + t;
    float sx = 0.f, sy = 0.f, sz = 0.f, sw = 0.f;
    float qx = 0.f, qy = 0.f, qz = 0.f, qw = 0.f;
#pragma unroll 8
    for (int r = 0; r < 64; r++) {
        float4 v = xg[(size_t)r * 128];
        sx += v.x; sy += v.y; sz += v.z; sw += v.w;
        qx = fmaf(v.x, v.x, qx); qy = fmaf(v.y, v.y, qy);
        qz = fmaf(v.z, v.z, qz); qw = fmaf(v.w, v.w, qw);
    }
    ((float4*)g_psum)[blockIdx.x * 128 + t] = make_float4(sx, sy, sz, sw);
    ((float4*)g_psq )[blockIdx.x * 128 + t] = make_float4(qx, qy, qz, qw);
}

// ---------------------------------------------------------------------------
// Kernel 2: fold 1024 partials -> 16 partials.
// ---------------------------------------------------------------------------
__global__ void __launch_bounds__(512) midreduce_kernel() {
    int T = blockIdx.x * 512 + threadIdx.x;
    int p = T >> 9;
    int f = T & 511;
    float s = 0.f, q = 0.f;
#pragma unroll 8
    for (int i = 0; i < 64; i++) {
        int idx = ((p * 64 + i) << 9) + f;
        s += g_psum[idx];
        q += g_psq [idx];
    }
    g_psum2[T] = s;
    g_psq2 [T] = q;
}

// ---------------------------------------------------------------------------
// Kernel 3: stats + Pp + bias partials, fused (warp-per-feature).
// ---------------------------------------------------------------------------
__global__ void __launch_bounds__(1024) pp_kernel(const float* __restrict__ P) {
    __shared__ float sred[32][33];
    int tid = threadIdx.x, warp = tid >> 5, lane = tid & 31;
    int f = blockIdx.x * 32 + warp;

    double sv = 0.0, qv = 0.0;
    if (lane < 16) {
        sv = (double)g_psum2[(lane << 9) + f];
        qv = (double)g_psq2 [(lane << 9) + f];
    }
#pragma unroll
    for (int off = 8; off > 0; off >>= 1) {
        sv += __shfl_down_sync(0xffffffffu, sv, off);
        qv += __shfl_down_sync(0xffffffffu, qv, off);
    }
    float meanf = 0.f, isig = 0.f;
    if (lane == 0) {
        const double Nd      = 65536.0;
        const double INV_N   = 1.0 / 65536.0;
        const double INV_NM1 = 1.0 / 65535.0;
        const double INV_TOT = 1.0 / 65536.0001;
        const double RATIO   = 65536.0 * INV_TOT;
        const double C1      = 1e-4 * 65536.0 * INV_TOT;
        double bm   = sv * INV_N;
        double bv   = (qv - Nd * bm * bm) * INV_NM1;
        double mean = bm * RATIO;
        double var  = (1e-4 + bv * Nd + bm * bm * C1) * INV_TOT;
        double v    = var + 1e-8;
        double r = (double)rsqrtf((float)v);
        r = r * (1.5 - 0.5 * v * r * r);
        meanf = (float)mean;
        isig  = (float)r;
    }
    meanf = __shfl_sync(0xffffffffu, meanf, 0);
    isig  = __shfl_sync(0xffffffffu, isig,  0);

    float pp = P[f * 32 + lane] * isig;
    g_Pp[f * 32 + lane] = pp;
    sred[warp][lane] = meanf * pp;
    __syncthreads();
    if (warp == 0) {
        float b = 0.f;
#pragma unroll
        for (int w = 0; w < 32; w++) b += sred[w][lane];
        g_biasp[blockIdx.x * 32 + lane] = b;
    }
}

// ---------------------------------------------------------------------------
// Kernel 4: projection + sign-bit keys (exact R12 structure: half-warp
// k-split, 2 bins/lane, 8-row tiles, cp.async double buffer, single
// uniform reduction phase, 2 barriers/iteration, no hash work).
// ---------------------------------------------------------------------------
#define P3_RB   8
#define P3_NBATCH (NROWS / P3_RB)    // 8192
// smem floats: 2 tiles (2*4096) + psum (8*32*32=8192) + bias 32
#define P3_SMEM  ((8192 + 8192 + 32) * 4)

__global__ void __launch_bounds__(512, 2) proj_kernel(const float* __restrict__ x) {
    extern __shared__ float smem[];
    float* xs0   = smem;             // 4096 floats (8 rows x 512)
    float* xs1   = smem + 4096;
    float* psum  = smem + 8192;      // [row][sub 0..31][bin 0..31]
    float* sbias = smem + 16384;     // 32 floats

    int tid  = threadIdx.x;
    int warp = tid >> 5;
    int lane = tid & 31;
    int half = lane >> 4;            // 0: k-sub lo, 1: k-sub hi
    int b0   = (lane & 15) << 1;     // first of this lane's two bins
    int sub  = (warp << 1) | half;   // global k-sub index 0..31 (16 k each)

    if (tid < NBINS) {
        float b = 0.f;
#pragma unroll
        for (int p = 0; p < 16; p++) b += g_biasp[p * 32 + tid];
        sbias[tid] = b;
    }

    // ppd0[i]/ppd1[i]: Pp k-pair (16*sub+2i, +1) for bins b0 / b0+1
    unsigned long long ppd0[8], ppd1[8];
    int k0 = sub << 4;
#pragma unroll
    for (int i = 0; i < 8; i++) {
        int k = k0 + 2 * i;
        float a0 = g_Pp[k * NBINS + b0],     a1 = g_Pp[(k + 1) * NBINS + b0];
        float c0 = g_Pp[k * NBINS + b0 + 1], c1 = g_Pp[(k + 1) * NBINS + b0 + 1];
        asm("mov.b64 %0, {%1, %2};" : "=l"(ppd0[i]) : "f"(a0), "f"(a1));
        asm("mov.b64 %0, {%1, %2};" : "=l"(ppd1[i]) : "f"(c0), "f"(c1));
    }

    unsigned sb0a = (unsigned)__cvta_generic_to_shared(xs0);
    unsigned sb1a = (unsigned)__cvta_generic_to_shared(xs1);

    // prologue: stream first tile (1024 float4, 512 threads -> 2 each)
    {
        const float4* xg = (const float4*)(x + (size_t)blockIdx.x * P3_RB * FEATD);
#pragma unroll
        for (int i = 0; i < 2; i++) {
            unsigned d = sb0a + (tid + 512 * i) * 16;
            asm volatile("cp.async.cg.shared.global [%0], [%1], 16;"
                         :: "r"(d), "l"(xg + tid + 512 * i));
        }
        asm volatile("cp.async.commit_group;");
        asm volatile("cp.async.wait_group 0;" ::: "memory");
    }
    __syncthreads();

    int cur = 0;

    for (int batch = blockIdx.x; batch < P3_NBATCH; batch += gridDim.x) {
        int nb = batch + gridDim.x;
        if (nb < P3_NBATCH) {
            const float4* xg = (const float4*)(x + (size_t)nb * P3_RB * FEATD);
            unsigned dst = cur ? sb0a : sb1a;
#pragma unroll
            for (int i = 0; i < 2; i++) {
                unsigned d = dst + (tid + 512 * i) * 16;
                asm volatile("cp.async.cg.shared.global [%0], [%1], 16;"
                             :: "r"(d), "l"(xg + tid + 512 * i));
            }
            asm volatile("cp.async.commit_group;");
        }

        const float* xsc = cur ? xs1 : xs0;
#pragma unroll
        for (int r = 0; r < P3_RB; r++) {
            const ulonglong2* xp = (const ulonglong2*)(xsc + r * FEATD + k0);
            unsigned long long a0 = 0ull, a1 = 0ull, c0 = 0ull, c1 = 0ull;
#pragma unroll
            for (int i = 0; i < 4; i++) {
                ulonglong2 v = xp[i];
                asm("fma.rn.f32x2 %0, %1, %2, %0;"
                    : "+l"(a0) : "l"(v.x), "l"(ppd0[2 * i]));
                asm("fma.rn.f32x2 %0, %1, %2, %0;"
                    : "+l"(a1) : "l"(v.y), "l"(ppd0[2 * i + 1]));
                asm("fma.rn.f32x2 %0, %1, %2, %0;"
                    : "+l"(c0) : "l"(v.x), "l"(ppd1[2 * i]));
                asm("fma.rn.f32x2 %0, %1, %2, %0;"
                    : "+l"(c1) : "l"(v.y), "l"(ppd1[2 * i + 1]));
            }
            unsigned long long at, ct;
            asm("add.rn.f32x2 %0, %1, %2;" : "=l"(at) : "l"(a0), "l"(a1));
            asm("add.rn.f32x2 %0, %1, %2;" : "=l"(ct) : "l"(c0), "l"(c1));
            float alo, ahi, clo, chi;
            asm("mov.b64 {%0, %1}, %2;" : "=f"(alo), "=f"(ahi) : "l"(at));
            asm("mov.b64 {%0, %1}, %2;" : "=f"(clo), "=f"(chi) : "l"(ct));
            float2 pr = make_float2(alo + ahi, clo + chi);
            *(float2*)(psum + ((r * 32 + sub) * 32 + b0)) = pr;
        }
        __syncthreads();   // psum complete

        // single reduction phase: warp w (w<8) folds row w, ballots the key
        if (warp < P3_RB) {
            const float* pr = psum + warp * 32 * 32 + lane;
            float s0 = 0.f, s1 = 0.f, s2 = 0.f, s3 = 0.f;
#pragma unroll
            for (int c = 0; c < 8; c++) {
                s0 += pr[(c)      * 32];
                s1 += pr[(c + 8)  * 32];
                s2 += pr[(c + 16) * 32];
                s3 += pr[(c + 24) * 32];
            }
            float s = (s0 + s1) + (s2 + s3);
            unsigned key = __ballot_sync(0xffffffffu, s > sbias[lane]);
            if (lane == 0) g_keys[batch * P3_RB + warp] = key;
        }

        if (nb < P3_NBATCH)
            asm volatile("cp.async.wait_group 0;" ::: "memory");
        __syncthreads();   // next tile visible + psum WAR-safe
        cur ^= 1;
    }
}

// ---------------------------------------------------------------------------
// Kernel 5: hash-insert all keys. Packed entry = (key<<18)|count, so the
// claiming CAS performs the count increment too — unique keys (the ~100%
// case) cost ONE atomic. 25% load factor -> ~1.4 probes average.
// Deterministic: same key always lands in the same slot; counts are
// order-independent.
// ---------------------------------------------------------------------------
__global__ void __launch_bounds__(256) insert_kernel() {
    int i = blockIdx.x * 256 + threadIdx.x;
    unsigned key = g_keys[i];
    unsigned long long want = ((unsigned long long)key << 18) | 1ull;
    unsigned h = (key * 2654435761u) >> (32 - HASH_BITS);
    for (;;) {
        unsigned long long prev = atomicCAS(&g_hash[h], 0ull, want);
        if (prev == 0ull) {                       // claimed: count already 1
            g_slot[i] = (int)h;
            break;
        }
        if ((unsigned)(prev >> 18) == key) {      // same key: bump count
            atomicAdd(&g_hash[h], 1ull);
            g_slot[i] = (int)h;
            break;
        }
        h = (h + 1) & (HASH_SZ - 1);
    }
}

// ---------------------------------------------------------------------------
// Kernel 6: emit rewards for unique keys (count==1 -> 1.0); collect dup rows.
// ---------------------------------------------------------------------------
__global__ void __launch_bounds__(256) emit_kernel(float* __restrict__ out) {
    int i = blockIdx.x * 256 + threadIdx.x;
    unsigned cnt = (unsigned)(g_hash[g_slot[i]] & CNT_MASK);
    if (cnt == 1u) {
        out[i] = 1.0f;
    } else {
        int d = atomicAdd(&g_dupn, 1);
        if (d < DUP_CAP) g_dup[d] = i;
    }
}

// ---------------------------------------------------------------------------
// Kernel 7: exact occurrence rank for duplicated rows (rare; ~2 expected).
// ---------------------------------------------------------------------------
__global__ void __launch_bounds__(256) dupfix_kernel(float* __restrict__ out) {
    __shared__ int red[256];
    int n = g_dupn;
    if (n > DUP_CAP) n = DUP_CAP;
    int t = threadIdx.x;
    for (int d = blockIdx.x; d < n; d += gridDim.x) {
        int i = g_dup[d];
        unsigned key = g_keys[i];
        int c = 0;
        for (int j = t; j <= i; j += 256) c += (g_keys[j] == key) ? 1 : 0;
        red[t] = c;
        __syncthreads();
#pragma unroll
        for (int off = 128; off > 0; off >>= 1) {
            if (t < off) red[t] += red[t + off];
            __syncthreads();
        }
        if (t == 0) out[i] = rsqrtf((float)red[0]);
        __syncthreads();
    }
}

// ---------------------------------------------------------------------------
extern "C" void kernel_launch(void* const* d_in, const int* in_sizes, int n_in,
                              void* d_out, int out_size) {
    const float* x = (const float*)d_in[0];   // features  [64,1024,512]
    const float* P = (const float*)d_in[1];   // projection [512,32]
    if (n_in >= 2 && in_sizes[0] < in_sizes[1]) {
        const float* t = x; x = P; P = t;
    }
    float* out = (float*)d_out;

    cudaFuncSetAttribute(proj_kernel,
                         cudaFuncAttributeMaxDynamicSharedMemorySize, P3_SMEM);

    sums_kernel     <<<1024, 128>>>(x);
    midreduce_kernel<<<16,   512>>>();
    pp_kernel       <<<16,   1024>>>(P);
    proj_kernel     <<<296,  512, P3_SMEM>>>(x);
    insert_kernel   <<<NROWS / 256, 256>>>();
    emit_kernel     <<<NROWS / 256, 256>>>(out);
    dupfix_kernel   <<<16,   256>>>(out);
}